// round 15
// baseline (speedup 1.0000x reference)
#include <cuda_runtime.h>
#include <cuda_fp16.h>
#include <cstdint>

#define T_TABLES 4
#define B_BATCH  8192
#define L_LEN    50
#define D_DIM    128
#define VOCAB_N  100000
#define ROWS_TOTAL (T_TABLES * B_BATCH)   // 32768
#define GRID_N   (ROWS_TOTAL / 32)        // 1024 blocks
#define PREP_BLOCKS 129

// Scratch (device globals: allocation-free rule)
__device__ __half g_Wch[D_DIM * D_DIM];   // fp16 Wc: Wch[d][j] = (W3 W2 W1)[j][d]
__device__ float  g_bc[D_DIM];
__device__ int    g_ready;                // prep-done counter (reset each launch)
__device__ int    g_fin;                  // exit counter for reset

// ---- f32x2 packed helpers -------------------------------------------------
__device__ __forceinline__ void fma2(unsigned long long& d,
                                     unsigned long long a, unsigned long long b) {
    asm("fma.rn.f32x2 %0, %1, %2, %0;" : "+l"(d) : "l"(a), "l"(b));
}
__device__ __forceinline__ unsigned long long add2(unsigned long long a,
                                                   unsigned long long b) {
    unsigned long long r;
    asm("add.rn.f32x2 %0, %1, %2;" : "=l"(r) : "l"(a), "l"(b));
    return r;
}
__device__ __forceinline__ float2 upk(unsigned long long v) {
    float2 r;
    asm("mov.b64 {%0, %1}, %2;" : "=f"(r.x), "=f"(r.y) : "l"(v));
    return r;
}
// half2 (packed in u32) -> f32x2 operand (u64)
__device__ __forceinline__ unsigned long long h2w(uint32_t h2pack) {
    __half2 h = *(__half2*)&h2pack;
    float2 f = __half22float2(h);
    unsigned long long r;
    asm("mov.b64 %0, {%1, %2};" : "=l"(r) : "f"(f.x), "f"(f.y));
    return r;
}

// ---------------------------------------------------------------------------
// Fused, self-contained (no separate prep launch):
//   blocks 0..127 compute Wc column d = W3·W2·W1[:,d] (fp16 store);
//   block 128 computes bc. Then ALL blocks run Phase A (gather, ~60us),
//   wait on g_ready (trivially satisfied by then), run Phase B.
//   Last exiting block resets the counters (graph-replay determinism).
// grid = 1024 x 256; 33 KB smem; natural regs; no reg cap.
// ---------------------------------------------------------------------------
__global__ __launch_bounds__(256)
void fused_kernel(const int* __restrict__ indices,
                  const int* __restrict__ lengths,
                  const float* __restrict__ tables,
                  const float* __restrict__ W1, const float* __restrict__ b1,
                  const float* __restrict__ W2, const float* __restrict__ b2,
                  const float* __restrict__ W3, const float* __restrict__ b3,
                  float* __restrict__ out) {
    __shared__ float sp[8 * 4 * 2 * D_DIM];        // 32 KB: per-warp duplicated pooled
    __shared__ float pv[D_DIM];                    // prep scratch
    __shared__ float py[D_DIM];

    const int tid  = threadIdx.x;
    const int warp = tid >> 5, lane = tid & 31;
    const int row0 = (blockIdx.x * 8 + warp) * 4;
    float* my = sp + warp * 4 * 2 * D_DIM;         // 4 rows x 256 floats (dup pairs)

    // ---- Phase 0 (blocks 0..128): collapsed-weight prep ----
    if (blockIdx.x < PREP_BLOCKS) {
        if (tid < D_DIM) {
            if (blockIdx.x < D_DIM) {
                const int d = blockIdx.x;
                pv[tid] = W1[tid * D_DIM + d];              // W1 column d
            } else {
                pv[tid] = b1[tid];
            }
        }
        __syncthreads();
        if (tid < D_DIM) {
            const float4* W2r = (const float4*)(W2 + tid * D_DIM);
            float s = (blockIdx.x < D_DIM) ? 0.f : b2[tid];
#pragma unroll
            for (int k = 0; k < 32; ++k) {                  // MLP=32
                const float4 w = __ldg(&W2r[k]);
                s += w.x * pv[k * 4] + w.y * pv[k * 4 + 1];
                s += w.z * pv[k * 4 + 2] + w.w * pv[k * 4 + 3];
            }
            py[tid] = s;
        }
        __syncthreads();
        if (tid < D_DIM) {
            const float4* W3r = (const float4*)(W3 + tid * D_DIM);
            float s2 = (blockIdx.x < D_DIM) ? 0.f : b3[tid];
#pragma unroll
            for (int k = 0; k < 32; ++k) {
                const float4 w = __ldg(&W3r[k]);
                s2 += w.x * py[k * 4] + w.y * py[k * 4 + 1];
                s2 += w.z * py[k * 4 + 2] + w.w * py[k * 4 + 3];
            }
            if (blockIdx.x < D_DIM) g_Wch[blockIdx.x * D_DIM + tid] = __float2half(s2);
            else                    g_bc[tid] = s2;
        }
        __syncthreads();
        if (tid == 0) {
            __threadfence();                                // publish Wch/bc
            atomicAdd(&g_ready, 1);
        }
    }

    // ---- Phase A: gather + pool 4 rows (lane owns one float4 of D) ----
#pragma unroll 1
    for (int r = 0; r < 4; ++r) {
        const int g   = row0 + r;
        const int t   = g >> 13;                    // B = 8192
        const int len = lengths[g];
        const int* idxp = indices + (size_t)g * L_LEN;

        const int i_lo = idxp[lane];
        const int i_hi = (lane < (L_LEN - 32)) ? idxp[32 + lane] : 0;

        const float4* tab =
            (const float4*)tables + (size_t)t * ((size_t)VOCAB_N * (D_DIM / 4));

        ulonglong2 A0 = {0ull, 0ull}, A1 = A0, A2 = A0, A3 = A0;

        auto getidx = [&](int p) -> int {
            return (p < 32) ? __shfl_sync(0xffffffffu, i_lo, p)
                            : __shfl_sync(0xffffffffu, i_hi, p - 32);
        };

        int l = 0;
        for (; l + 3 < len; l += 4) {
            const int j0 = getidx(l + 0);
            const int j1 = getidx(l + 1);
            const int j2 = getidx(l + 2);
            const int j3 = getidx(l + 3);
            const ulonglong2 v0 = __ldcg((const ulonglong2*)(tab + (size_t)j0 * 32 + lane));
            const ulonglong2 v1 = __ldcg((const ulonglong2*)(tab + (size_t)j1 * 32 + lane));
            const ulonglong2 v2 = __ldcg((const ulonglong2*)(tab + (size_t)j2 * 32 + lane));
            const ulonglong2 v3 = __ldcg((const ulonglong2*)(tab + (size_t)j3 * 32 + lane));
            A0.x = add2(A0.x, v0.x); A0.y = add2(A0.y, v0.y);
            A1.x = add2(A1.x, v1.x); A1.y = add2(A1.y, v1.y);
            A2.x = add2(A2.x, v2.x); A2.y = add2(A2.y, v2.y);
            A3.x = add2(A3.x, v3.x); A3.y = add2(A3.y, v3.y);
        }
        for (; l < len; ++l) {
            const int j0 = getidx(l);
            const ulonglong2 v0 = __ldcg((const ulonglong2*)(tab + (size_t)j0 * 32 + lane));
            A0.x = add2(A0.x, v0.x); A0.y = add2(A0.y, v0.y);
        }

        const unsigned long long rlo = add2(add2(A0.x, A1.x), add2(A2.x, A3.x));
        const unsigned long long rhi = add2(add2(A0.y, A1.y), add2(A2.y, A3.y));
        const float2 f0 = upk(rlo);     // (p[c], p[c+1])   c = lane*4
        const float2 f1 = upk(rhi);     // (p[c+2], p[c+3])

        // duplicated-pair layout: pos 2d, 2d+1 both hold p[d]
        float4 s0, s1;
        s0.x = f0.x; s0.y = f0.x; s0.z = f0.y; s0.w = f0.y;
        s1.x = f1.x; s1.y = f1.x; s1.z = f1.y; s1.w = f1.y;
        *(float4*)&my[r * 2 * D_DIM + lane * 8]     = s0;
        *(float4*)&my[r * 2 * D_DIM + lane * 8 + 4] = s1;
    }

    // ---- wait for prep (satisfied long ago for virtually all blocks) ----
    if (tid == 0) {
        while (*(volatile int*)&g_ready < PREP_BLOCKS) __nanosleep(100);
    }
    __syncthreads();
    __threadfence();                                // acquire side

    // ---- Phase B: out[r][:] = pooled[r][:] @ Wc + bc  (fp16 W, f32 acc) ----
    const ulonglong2 bc2 = __ldg((const ulonglong2*)g_bc + lane);
    unsigned long long olo[4], ohi[4];
#pragma unroll
    for (int r = 0; r < 4; ++r) { olo[r] = bc2.x; ohi[r] = bc2.y; }

    // row d of Wch: 128 halves = 32 uint2; lane owns cols lane*4..lane*4+3
    const uint2* WcH = (const uint2*)g_Wch;

#pragma unroll 4
    for (int d4 = 0; d4 < 32; ++d4) {
        const uint2 h0 = __ldg(&WcH[(size_t)(d4 * 4 + 0) * 32 + lane]);
        const uint2 h1 = __ldg(&WcH[(size_t)(d4 * 4 + 1) * 32 + lane]);
        const uint2 h2 = __ldg(&WcH[(size_t)(d4 * 4 + 2) * 32 + lane]);
        const uint2 h3 = __ldg(&WcH[(size_t)(d4 * 4 + 3) * 32 + lane]);
        const unsigned long long w0x = h2w(h0.x), w0y = h2w(h0.y);
        const unsigned long long w1x = h2w(h1.x), w1y = h2w(h1.y);
        const unsigned long long w2x = h2w(h2.x), w2y = h2w(h2.y);
        const unsigned long long w3x = h2w(h3.x), w3y = h2w(h3.y);
#pragma unroll
        for (int r = 0; r < 4; ++r) {
            const ulonglong2 q0 = *(const ulonglong2*)&my[r * 2 * D_DIM + d4 * 8];
            const ulonglong2 q1 = *(const ulonglong2*)&my[r * 2 * D_DIM + d4 * 8 + 4];
            fma2(olo[r], q0.x, w0x); fma2(ohi[r], q0.x, w0y);
            fma2(olo[r], q0.y, w1x); fma2(ohi[r], q0.y, w1y);
            fma2(olo[r], q1.x, w2x); fma2(ohi[r], q1.x, w2y);
            fma2(olo[r], q1.y, w3x); fma2(ohi[r], q1.y, w3y);
        }
    }

#pragma unroll
    for (int r = 0; r < 4; ++r) {
        ulonglong2 res; res.x = olo[r]; res.y = ohi[r];
        __stcs((ulonglong2*)(out + (size_t)(row0 + r) * D_DIM + lane * 4), res);
    }

    // ---- reset counters for next (graph-replayed) launch ----
    __syncthreads();
    if (tid == 0) {
        __threadfence();
        const int done = atomicAdd(&g_fin, 1);
        if (done == GRID_N - 1) {                   // last block out resets
            g_ready = 0;
            g_fin   = 0;
            __threadfence();
        }
    }
}

// ---------------------------------------------------------------------------
extern "C" void kernel_launch(void* const* d_in, const int* in_sizes, int n_in,
                              void* d_out, int out_size) {
    const int*   indices = (const int*)d_in[0];
    const int*   lengths = (const int*)d_in[1];
    const float* tables  = (const float*)d_in[2];
    const float* W1      = (const float*)d_in[3];
    const float* b1      = (const float*)d_in[4];
    const float* W2      = (const float*)d_in[5];
    const float* b2      = (const float*)d_in[6];
    const float* W3      = (const float*)d_in[7];
    const float* b3      = (const float*)d_in[8];
    float* out = (float*)d_out;

    fused_kernel<<<GRID_N, 256>>>(indices, lengths, tables,
                                  W1, b1, W2, b2, W3, b3, out);
}

// round 17
// speedup vs baseline: 1.0041x; 1.0041x over previous
#include <cuda_runtime.h>
#include <cuda_fp16.h>
#include <cstdint>

#define T_TABLES 4
#define B_BATCH  8192
#define L_LEN    50
#define D_DIM    128
#define VOCAB_N  100000
#define ROWS_TOTAL (T_TABLES * B_BATCH)   // 32768
#define GRID_N   (ROWS_TOTAL / 32)        // 1024 blocks
#define WARPS_TOTAL (GRID_N * 8)          // 8192 warps
#define PREP_BLOCKS 129

// Scratch (device globals: allocation-free rule)
__device__ __half g_Wch[D_DIM * D_DIM];   // fp16 Wc: Wch[d][j] = (W3 W2 W1)[j][d]
__device__ float  g_bc[D_DIM];
__device__ int    g_ready;                // prep-done counter (reset each launch)
__device__ int    g_fin;                  // per-warp exit counter for reset

// ---- f32x2 packed helpers -------------------------------------------------
__device__ __forceinline__ void fma2(unsigned long long& d,
                                     unsigned long long a, unsigned long long b) {
    asm("fma.rn.f32x2 %0, %1, %2, %0;" : "+l"(d) : "l"(a), "l"(b));
}
__device__ __forceinline__ unsigned long long add2(unsigned long long a,
                                                   unsigned long long b) {
    unsigned long long r;
    asm("add.rn.f32x2 %0, %1, %2;" : "=l"(r) : "l"(a), "l"(b));
    return r;
}
__device__ __forceinline__ float2 upk(unsigned long long v) {
    float2 r;
    asm("mov.b64 {%0, %1}, %2;" : "=f"(r.x), "=f"(r.y) : "l"(v));
    return r;
}
// half2 (packed in u32) -> f32x2 operand (u64)
__device__ __forceinline__ unsigned long long h2w(uint32_t h2pack) {
    __half2 h = *(__half2*)&h2pack;
    float2 f = __half22float2(h);
    unsigned long long r;
    asm("mov.b64 %0, {%1, %2};" : "=l"(r) : "f"(f.x), "f"(f.y));
    return r;
}

// ---------------------------------------------------------------------------
// Fused megakernel v2 — WARP-SCOPED prep wait (no block barrier between
// Phase A and Phase B; block-wide sync there cost +15us in v1):
//   blocks 0..127: Wc column d = W3·W2·W1[:,d] (fp16); block 128: bc.
//   All blocks: Phase A gather (~60us) -> per-warp poll of g_ready ->
//   Phase B. Globally-last warp resets counters (graph-replay safe).
// grid = 1024 x 256; 34 KB smem; natural regs.
// ---------------------------------------------------------------------------
__global__ __launch_bounds__(256)
void fused_kernel(const int* __restrict__ indices,
                  const int* __restrict__ lengths,
                  const float* __restrict__ tables,
                  const float* __restrict__ W1, const float* __restrict__ b1,
                  const float* __restrict__ W2, const float* __restrict__ b2,
                  const float* __restrict__ W3, const float* __restrict__ b3,
                  float* __restrict__ out) {
    __shared__ float sp[8 * 4 * 2 * D_DIM];        // 32 KB: per-warp duplicated pooled
    __shared__ float pv[D_DIM];                    // prep scratch
    __shared__ float py[D_DIM];

    const int tid  = threadIdx.x;
    const int warp = tid >> 5, lane = tid & 31;
    const int row0 = (blockIdx.x * 8 + warp) * 4;
    float* my = sp + warp * 4 * 2 * D_DIM;         // 4 rows x 256 floats (dup pairs)

    // ---- Phase 0 (blocks 0..128): collapsed-weight prep ----
    if (blockIdx.x < PREP_BLOCKS) {
        if (tid < D_DIM) {
            pv[tid] = (blockIdx.x < D_DIM) ? W1[tid * D_DIM + blockIdx.x] : b1[tid];
        }
        __syncthreads();
        if (tid < D_DIM) {
            const float4* W2r = (const float4*)(W2 + tid * D_DIM);
            float s = (blockIdx.x < D_DIM) ? 0.f : b2[tid];
#pragma unroll
            for (int k = 0; k < 32; ++k) {                  // MLP=32
                const float4 w = __ldg(&W2r[k]);
                s += w.x * pv[k * 4] + w.y * pv[k * 4 + 1];
                s += w.z * pv[k * 4 + 2] + w.w * pv[k * 4 + 3];
            }
            py[tid] = s;
        }
        __syncthreads();
        if (tid < D_DIM) {
            const float4* W3r = (const float4*)(W3 + tid * D_DIM);
            float s2 = (blockIdx.x < D_DIM) ? 0.f : b3[tid];
#pragma unroll
            for (int k = 0; k < 32; ++k) {
                const float4 w = __ldg(&W3r[k]);
                s2 += w.x * py[k * 4] + w.y * py[k * 4 + 1];
                s2 += w.z * py[k * 4 + 2] + w.w * py[k * 4 + 3];
            }
            if (blockIdx.x < D_DIM) g_Wch[blockIdx.x * D_DIM + tid] = __float2half(s2);
            else                    g_bc[tid] = s2;
        }
        __syncthreads();
        if (tid == 0) {
            __threadfence();                                // publish Wch/bc
            atomicAdd(&g_ready, 1);
        }
        // NOTE: no further block-wide sync — warps proceed independently.
    }

    // ---- Phase A: gather + pool 4 rows (lane owns one float4 of D) ----
#pragma unroll 1
    for (int r = 0; r < 4; ++r) {
        const int g   = row0 + r;
        const int t   = g >> 13;                    // B = 8192
        const int len = lengths[g];
        const int* idxp = indices + (size_t)g * L_LEN;

        const int i_lo = idxp[lane];
        const int i_hi = (lane < (L_LEN - 32)) ? idxp[32 + lane] : 0;

        const float4* tab =
            (const float4*)tables + (size_t)t * ((size_t)VOCAB_N * (D_DIM / 4));

        ulonglong2 A0 = {0ull, 0ull}, A1 = A0, A2 = A0, A3 = A0;

        auto getidx = [&](int p) -> int {
            return (p < 32) ? __shfl_sync(0xffffffffu, i_lo, p)
                            : __shfl_sync(0xffffffffu, i_hi, p - 32);
        };

        int l = 0;
        for (; l + 3 < len; l += 4) {
            const int j0 = getidx(l + 0);
            const int j1 = getidx(l + 1);
            const int j2 = getidx(l + 2);
            const int j3 = getidx(l + 3);
            const ulonglong2 v0 = __ldcg((const ulonglong2*)(tab + (size_t)j0 * 32 + lane));
            const ulonglong2 v1 = __ldcg((const ulonglong2*)(tab + (size_t)j1 * 32 + lane));
            const ulonglong2 v2 = __ldcg((const ulonglong2*)(tab + (size_t)j2 * 32 + lane));
            const ulonglong2 v3 = __ldcg((const ulonglong2*)(tab + (size_t)j3 * 32 + lane));
            A0.x = add2(A0.x, v0.x); A0.y = add2(A0.y, v0.y);
            A1.x = add2(A1.x, v1.x); A1.y = add2(A1.y, v1.y);
            A2.x = add2(A2.x, v2.x); A2.y = add2(A2.y, v2.y);
            A3.x = add2(A3.x, v3.x); A3.y = add2(A3.y, v3.y);
        }
        for (; l < len; ++l) {
            const int j0 = getidx(l);
            const ulonglong2 v0 = __ldcg((const ulonglong2*)(tab + (size_t)j0 * 32 + lane));
            A0.x = add2(A0.x, v0.x); A0.y = add2(A0.y, v0.y);
        }

        const unsigned long long rlo = add2(add2(A0.x, A1.x), add2(A2.x, A3.x));
        const unsigned long long rhi = add2(add2(A0.y, A1.y), add2(A2.y, A3.y));
        const float2 f0 = upk(rlo);     // (p[c], p[c+1])   c = lane*4
        const float2 f1 = upk(rhi);     // (p[c+2], p[c+3])

        // duplicated-pair layout: pos 2d, 2d+1 both hold p[d]
        float4 s0, s1;
        s0.x = f0.x; s0.y = f0.x; s0.z = f0.y; s0.w = f0.y;
        s1.x = f1.x; s1.y = f1.x; s1.z = f1.y; s1.w = f1.y;
        *(float4*)&my[r * 2 * D_DIM + lane * 8]     = s0;
        *(float4*)&my[r * 2 * D_DIM + lane * 8 + 4] = s1;
    }

    // ---- per-WARP wait for prep (no cross-warp coupling) ----
    if (lane == 0) {
        while (*(volatile int*)&g_ready < PREP_BLOCKS) __nanosleep(64);
    }
    __syncwarp();
    __threadfence();                                // acquire before Wch/bc reads

    // ---- Phase B: out[r][:] = pooled[r][:] @ Wc + bc  (fp16 W, f32 acc) ----
    const ulonglong2 bc2 = __ldg((const ulonglong2*)g_bc + lane);
    unsigned long long olo[4], ohi[4];
#pragma unroll
    for (int r = 0; r < 4; ++r) { olo[r] = bc2.x; ohi[r] = bc2.y; }

    // row d of Wch: 128 halves = 32 uint2; lane owns cols lane*4..lane*4+3
    const uint2* WcH = (const uint2*)g_Wch;

#pragma unroll 4
    for (int d4 = 0; d4 < 32; ++d4) {
        const uint2 h0 = __ldg(&WcH[(size_t)(d4 * 4 + 0) * 32 + lane]);
        const uint2 h1 = __ldg(&WcH[(size_t)(d4 * 4 + 1) * 32 + lane]);
        const uint2 h2 = __ldg(&WcH[(size_t)(d4 * 4 + 2) * 32 + lane]);
        const uint2 h3 = __ldg(&WcH[(size_t)(d4 * 4 + 3) * 32 + lane]);
        const unsigned long long w0x = h2w(h0.x), w0y = h2w(h0.y);
        const unsigned long long w1x = h2w(h1.x), w1y = h2w(h1.y);
        const unsigned long long w2x = h2w(h2.x), w2y = h2w(h2.y);
        const unsigned long long w3x = h2w(h3.x), w3y = h2w(h3.y);
#pragma unroll
        for (int r = 0; r < 4; ++r) {
            const ulonglong2 q0 = *(const ulonglong2*)&my[r * 2 * D_DIM + d4 * 8];
            const ulonglong2 q1 = *(const ulonglong2*)&my[r * 2 * D_DIM + d4 * 8 + 4];
            fma2(olo[r], q0.x, w0x); fma2(ohi[r], q0.x, w0y);
            fma2(olo[r], q0.y, w1x); fma2(ohi[r], q0.y, w1y);
            fma2(olo[r], q1.x, w2x); fma2(ohi[r], q1.x, w2y);
            fma2(olo[r], q1.y, w3x); fma2(ohi[r], q1.y, w3y);
        }
    }

#pragma unroll
    for (int r = 0; r < 4; ++r) {
        ulonglong2 res; res.x = olo[r]; res.y = ohi[r];
        __stcs((ulonglong2*)(out + (size_t)(row0 + r) * D_DIM + lane * 4), res);
    }

    // ---- per-warp exit count; globally-last warp resets (replay-safe).
    // Any warp still waiting on g_ready has NOT incremented g_fin, so the
    // last-warp condition cannot fire while anyone is still waiting.
    __syncwarp();
    if (lane == 0) {
        __threadfence();
        const int done = atomicAdd(&g_fin, 1);
        if (done == WARPS_TOTAL - 1) {
            g_ready = 0;
            g_fin   = 0;
            __threadfence();
        }
    }
}

// ---------------------------------------------------------------------------
extern "C" void kernel_launch(void* const* d_in, const int* in_sizes, int n_in,
                              void* d_out, int out_size) {
    const int*   indices = (const int*)d_in[0];
    const int*   lengths = (const int*)d_in[1];
    const float* tables  = (const float*)d_in[2];
    const float* W1      = (const float*)d_in[3];
    const float* b1      = (const float*)d_in[4];
    const float* W2      = (const float*)d_in[5];
    const float* b2      = (const float*)d_in[6];
    const float* W3      = (const float*)d_in[7];
    const float* b3      = (const float*)d_in[8];
    float* out = (float*)d_out;

    fused_kernel<<<GRID_N, 256>>>(indices, lengths, tables,
                                  W1, b1, W2, b2, W3, b3, out);
}